// round 10
// baseline (speedup 1.0000x reference)
#include <cuda_runtime.h>
#include <math.h>

#define BB 2
#define NN 262144
#define KK 9      // K+1 slots
#define DD 64
#define SS 64
#define BG_BOUND 1.0f
#define SCALE_F 0.125f

// ---------------------------------------------------------------------------
// Folded per-batch operands; computed on device, copied into __constant__.
// Warp-uniform indices in the main kernel -> LDCU (uniform const port).
// ---------------------------------------------------------------------------
struct __align__(16) PreData {
    float M[BB][KK][DD];   // M = K @ Wq          (logit matrix)
    float P[BB][KK][DD];   // P = slots_full @ out_w^T
    float c[BB][KK];       // c = K @ Wq_b
    float ob[DD];          // out_b
    float ds;              // exp(density_scale)
};
__device__    PreData g_pre;
__constant__  PreData c_pre;

// ---------------------------------------------------------------------------
// Precompute: one block per (batch, slot) pair -> 18 blocks, 64 threads.
// ---------------------------------------------------------------------------
__global__ __launch_bounds__(64)
void precompute(const float* __restrict__ slots,
                const float* __restrict__ empty_slot,
                const float* __restrict__ Wq_w,
                const float* __restrict__ Wq_b,
                const float* __restrict__ Wk_w,
                const float* __restrict__ Wk_b,
                const float* __restrict__ out_w,
                const float* __restrict__ out_b,
                const float* __restrict__ dscale)
{
    __shared__ float sSlot[SS];
    __shared__ float sK[DD];

    const int b = blockIdx.x / KK;
    const int j = blockIdx.x % KK;
    const int d = threadIdx.x;

    sSlot[d] = (j == 0) ? empty_slot[d]
                        : slots[((size_t)b * (KK - 1) + (j - 1)) * SS + d];
    __syncthreads();

    const float4* wk4 = reinterpret_cast<const float4*>(Wk_w  + d * SS);
    const float4* ow4 = reinterpret_cast<const float4*>(out_w + d * SS);
    float kk = Wk_b[d];
    float pp = 0.f;
#pragma unroll
    for (int i = 0; i < SS / 4; i++) {
        const float4 wv = wk4[i];
        const float4 ov = ow4[i];
        const float s0 = sSlot[4 * i], s1 = sSlot[4 * i + 1];
        const float s2 = sSlot[4 * i + 2], s3 = sSlot[4 * i + 3];
        kk = fmaf(s0, wv.x, fmaf(s1, wv.y, fmaf(s2, wv.z, fmaf(s3, wv.w, kk))));
        pp = fmaf(s0, ov.x, fmaf(s1, ov.y, fmaf(s2, ov.z, fmaf(s3, ov.w, pp))));
    }
    sK[d] = kk;
    g_pre.P[b][j][d] = pp;

    if (blockIdx.x == 0) {
        g_pre.ob[d] = out_b[d];
        if (d == 0) g_pre.ds = __expf(dscale[0]);
    }
    __syncthreads();

    float m = 0.f;
#pragma unroll 8
    for (int dd = 0; dd < DD; dd++)
        m = fmaf(sK[dd], Wq_w[dd * DD + d], m);
    g_pre.M[b][j][d] = m;

    if (d == 0) {
        float cc = 0.f;
        for (int dd = 0; dd < DD; dd++)
            cc = fmaf(Wq_b[dd], sK[dd], cc);
        g_pre.c[b][j] = cc;
    }
}

// ---------------------------------------------------------------------------
// Main kernel: 256 threads / 256 points per block.
// Double-buffered conflict-free transpose tiles + register prefetch:
// one __syncthreads per tile (8 total), every LDG hoisted a tile ahead.
// ---------------------------------------------------------------------------
__global__ __launch_bounds__(256)
void joint_decoder_main(const float* __restrict__ pf,
                        const float* __restrict__ coor,
                        float* __restrict__ xo,
                        float* __restrict__ wout,
                        float* __restrict__ sig)
{
    __shared__ float4 sT4[2][4][258];    // two conflict-free transpose tiles
    __shared__ float  sW[256 * KK];      // staged w for coalesced stores
    __shared__ float4 sCoor4[192];       // 256 pts * 3 floats

    const int tid = threadIdx.x;
    const int p0  = blockIdx.x * 256;
    const int b   = blockIdx.x >> 10;    // 1024 blocks per batch
    const int p   = p0 + tid;
    const int tc  = tid & 3;             // chunk lane
    const int tp  = tid >> 2;            // 0..63

    if (tid < 192)
        sCoor4[tid] = reinterpret_cast<const float4*>(coor + (size_t)p0 * 3)[tid];

    const float4* pf4 = reinterpret_cast<const float4*>(pf + (size_t)p0 * DD);

    // ---- Phase 1: logits, 4 tiles, double-buffered, reg-prefetched ----
    float acc[KK];
#pragma unroll
    for (int j = 0; j < KK; j++) acc[j] = 0.f;

    float4 r0, r1, r2, r3;
    // preload tile 0
    r0 = pf4[(tp)       * 16 + 0 + tc];
    r1 = pf4[(64  + tp) * 16 + 0 + tc];
    r2 = pf4[(128 + tp) * 16 + 0 + tc];
    r3 = pf4[(192 + tp) * 16 + 0 + tc];

#pragma unroll
    for (int it = 0; it < 4; it++) {
        const int buf = it & 1;
        sT4[buf][tc][tp]       = r0;
        sT4[buf][tc][64  + tp] = r1;
        sT4[buf][tc][128 + tp] = r2;
        sT4[buf][tc][192 + tp] = r3;
        __syncthreads();
        if (it < 3) {                    // prefetch next tile (hidden by FMAs)
            const int o = (it + 1) * 4 + tc;
            r0 = pf4[(tp)       * 16 + o];
            r1 = pf4[(64  + tp) * 16 + o];
            r2 = pf4[(128 + tp) * 16 + o];
            r3 = pf4[(192 + tp) * 16 + o];
        }
#pragma unroll
        for (int ii = 0; ii < 4; ii++) {
            const float4 x = sT4[buf][ii][tid];
            const int i4 = (it * 4 + ii) * 4;
#pragma unroll
            for (int j = 0; j < KK; j++) {
                acc[j] = fmaf(x.x, c_pre.M[b][j][i4 + 0],
                         fmaf(x.y, c_pre.M[b][j][i4 + 1],
                         fmaf(x.z, c_pre.M[b][j][i4 + 2],
                         fmaf(x.w, c_pre.M[b][j][i4 + 3], acc[j]))));
            }
        }
    }

    float logit[KK];
#pragma unroll
    for (int j = 0; j < KK; j++)
        logit[j] = (acc[j] + c_pre.c[b][j]) * SCALE_F;

    // ---- force_bg mask (coor staged coalesced; ordered by phase-1 syncs) ----
    const float* cp = reinterpret_cast<const float*>(sCoor4) + tid * 3;
    const bool inb = (fabsf(cp[0]) <= BG_BOUND) && (fabsf(cp[1]) <= BG_BOUND) &&
                     (fabsf(cp[2]) <= BG_BOUND);

    // ---- masked softmax ----
    float mx = fmaxf(logit[0], logit[1]);
    if (inb) {
#pragma unroll
        for (int j = 2; j < KK; j++) mx = fmaxf(mx, logit[j]);
    }
    float w[KK];
    w[0] = __expf(logit[0] - mx);
    w[1] = __expf(logit[1] - mx);
    float s = w[0] + w[1];
#pragma unroll
    for (int j = 2; j < KK; j++) {
        const float e = inb ? __expf(logit[j] - mx) : 0.f;
        w[j] = e;
        s += e;
    }
    const float inv = __frcp_rn(s);
#pragma unroll
    for (int j = 0; j < KK; j++) w[j] *= inv;

    // ---- density + scalar outputs ----
    float sg = 0.f;
#pragma unroll
    for (int j = 1; j < KK; j++) sg = fmaf(fmaxf(logit[j], 0.f), w[j], sg);
    sig[p] = sg * c_pre.ds;

#pragma unroll
    for (int j = 0; j < KK; j++) sW[tid * KK + j] = w[j];   // stride 9: no conflicts

    // ---- Phase 2: xo, 4 tiles, double-buffered, 1 sync/tile ----
    // Safety: phase-2 STS(it) into buf[it&1] happens after sync(it-1), by which
    // point every thread has drained tile it-2 from that buffer (and phase-1's
    // last consumes finished before sync(3)).
    float4* xo4 = reinterpret_cast<float4*>(xo + (size_t)p0 * DD);
#pragma unroll
    for (int it = 0; it < 4; it++) {
        const int buf = it & 1;
#pragma unroll
        for (int ii = 0; ii < 4; ii++) {
            const int i4 = (it * 4 + ii) * 4;
            float4 o;
            o.x = c_pre.ob[i4 + 0];
            o.y = c_pre.ob[i4 + 1];
            o.z = c_pre.ob[i4 + 2];
            o.w = c_pre.ob[i4 + 3];
#pragma unroll
            for (int j = 0; j < KK; j++) {
                o.x = fmaf(w[j], c_pre.P[b][j][i4 + 0], o.x);
                o.y = fmaf(w[j], c_pre.P[b][j][i4 + 1], o.y);
                o.z = fmaf(w[j], c_pre.P[b][j][i4 + 2], o.z);
                o.w = fmaf(w[j], c_pre.P[b][j][i4 + 3], o.w);
            }
            sT4[buf][ii][tid] = o;
        }
        __syncthreads();
        const int o = it * 4 + tc;
        xo4[(tp)       * 16 + o] = sT4[buf][tc][tp];
        xo4[(64  + tp) * 16 + o] = sT4[buf][tc][64  + tp];
        xo4[(128 + tp) * 16 + o] = sT4[buf][tc][128 + tp];
        xo4[(192 + tp) * 16 + o] = sT4[buf][tc][192 + tp];
    }

    // ---- w out: float4-coalesced copy (ordered by the phase-2 syncs) ----
    {
        const float4* sw4 = reinterpret_cast<const float4*>(sW);
        float4* wg4 = reinterpret_cast<float4*>(wout + (size_t)p0 * KK);
        wg4[tid]       = sw4[tid];
        wg4[tid + 256] = sw4[tid + 256];
        if (tid < 64) wg4[tid + 512] = sw4[tid + 512];
    }
}

// ---------------------------------------------------------------------------
// Launch
// ---------------------------------------------------------------------------
extern "C" void kernel_launch(void* const* d_in, const int* in_sizes, int n_in,
                              void* d_out, int out_size)
{
    const float* pf     = (const float*)d_in[0];   // point_feats [B,N,D]
    const float* slots  = (const float*)d_in[2];   // [B,K,S]
    const float* coor   = (const float*)d_in[3];   // [B,N,3]
    const float* empty  = (const float*)d_in[4];   // [1,1,S]
    const float* Wq_w   = (const float*)d_in[5];
    const float* Wq_b   = (const float*)d_in[6];
    const float* Wk_w   = (const float*)d_in[7];
    const float* Wk_b   = (const float*)d_in[8];
    const float* out_w  = (const float*)d_in[9];
    const float* out_b  = (const float*)d_in[10];
    const float* dscale = (const float*)d_in[11];

    float* out  = (float*)d_out;
    float* xo   = out;                              // [B,N,64]
    float* wout = out + (size_t)BB * NN * DD;       // [B,N,9]
    float* sig  = wout + (size_t)BB * NN * KK;      // [B,N]

    precompute<<<BB * KK, 64>>>(slots, empty, Wq_w, Wq_b, Wk_w, Wk_b,
                                out_w, out_b, dscale);

    void* g_pre_addr = nullptr;
    cudaGetSymbolAddress(&g_pre_addr, g_pre);
    cudaMemcpyToSymbolAsync(c_pre, g_pre_addr, sizeof(PreData), 0,
                            cudaMemcpyDeviceToDevice);

    joint_decoder_main<<<(BB * NN) / 256, 256>>>(pf, coor, xo, wout, sig);
}